// round 13
// baseline (speedup 1.0000x reference)
#include <cuda_runtime.h>
#include <cuda_bf16.h>
#include <math.h>

// Problem constants (fixed by setup_inputs)
#define BATCH   16
#define LEN     262144
#define NFFT    1024
#define HOP     256
#define NT      1025          // frames
#define NF      513           // rfft bins (valid)
#define NTP     65            // time patches
#define NFP     33            // freq patches
#define NP      2145          // patches per batch (33*65)
#define KSEL    643           // int(2145*0.3)
#define REFL2   (2*LEN - 2)   // 524286
#define NFRM    (BATCH*NT)    // 16400

// Scratch (static device memory; no allocation allowed)
__device__ float g_fpart[(size_t)NFRM * NFP * 3];   // per-frame patch partials [b][t][fp][3]
__device__ float g_bsel[BATCH];
__device__ float g_bkgs[BATCH];
__device__ int   g_bpos[BATCH];
__device__ float2 g_twa[64];     // W64^{n1*c}
__device__ float2 g_twb[512];    // [c*64+t] = W512^{n0*(k0+8c)}
__device__ float2 g_twu[512];    // e^{-i pi j/512}

// ---- complex helpers (float2) ----
__device__ __forceinline__ float2 cadd(float2 a, float2 b) { return make_float2(a.x + b.x, a.y + b.y); }
__device__ __forceinline__ float2 csub(float2 a, float2 b) { return make_float2(a.x - b.x, a.y - b.y); }
__device__ __forceinline__ float2 cmul(float2 a, float2 b) {
    return make_float2(a.x * b.x - a.y * b.y, a.x * b.y + a.y * b.x);
}
__device__ __forceinline__ float2 cmni(float2 a) { return make_float2(a.y, -a.x); }  // * (-i)

// FFT-8, natural-order in/out, straight-line on named registers.
__device__ __forceinline__ void fft8(float2& a0, float2& a1, float2& a2, float2& a3,
                                     float2& a4, float2& a5, float2& a6, float2& a7) {
    float2 ee0 = cadd(a0, a4), ee1 = csub(a0, a4);
    float2 oo0 = cadd(a2, a6), oo1 = csub(a2, a6);
    float2 E0 = cadd(ee0, oo0), E2 = csub(ee0, oo0);
    float2 tm = cmni(oo1);
    float2 E1 = cadd(ee1, tm), E3 = csub(ee1, tm);
    float2 fe0 = cadd(a1, a5), fe1 = csub(a1, a5);
    float2 fo0 = cadd(a3, a7), fo1 = csub(a3, a7);
    float2 O0 = cadd(fe0, fo0), O2 = csub(fe0, fo0);
    float2 um = cmni(fo1);
    float2 O1 = cadd(fe1, um), O3 = csub(fe1, um);
    const float s = 0.70710678118654752f;
    float2 w1o = make_float2(s * (O1.x + O1.y), s * (O1.y - O1.x));   // w8 * O1
    float2 w3o = make_float2(s * (O3.y - O3.x), -s * (O3.x + O3.y));  // w8^3 * O3
    float2 m2  = cmni(O2);
    a0 = cadd(E0, O0);  a4 = csub(E0, O0);
    a1 = cadd(E1, w1o); a5 = csub(E1, w1o);
    a2 = cadd(E2, m2);  a6 = csub(E2, m2);
    a3 = cadd(E3, w3o); a7 = csub(E3, w3o);
}

// group barrier: 64 threads (2 warps) of signal-group grp, named barrier 1..3
#define GBAR(grp) asm volatile("bar.sync %0, 64;" :: "r"((grp) + 1) : "memory")

// ---------------------------------------------------------------------------
// Init: build twiddle tables ONCE per launch (idempotent, deterministic).
// ---------------------------------------------------------------------------
__global__ void init_tw() {
    int idx = blockIdx.x * 128 + threadIdx.x;
    float sn, cs;
    if (idx < 64) {
        int n1 = idx >> 3, c = idx & 7;
        sincospif(-(float)(n1 * c) * (1.0f / 32.0f), &sn, &cs);
        g_twa[idx] = make_float2(cs, sn);
    } else if (idx < 576) {
        int e = idx - 64; int c = e >> 6; int t_ = e & 63;
        int n0b = t_ & 7, k0 = t_ >> 3;
        sincospif(-(float)(n0b * (k0 + 8 * c)) * (1.0f / 256.0f), &sn, &cs);
        g_twb[e] = make_float2(cs, sn);
    } else if (idx < 1088) {
        int j = idx - 576;
        sincospif(-(float)j * (1.0f / 512.0f), &sn, &cs);
        g_twu[j] = make_float2(cs, sn);
    }
}

// ---------------------------------------------------------------------------
// Frame kernel: ONE frame (b,t), all three signals, per block of 192 threads
// (3 groups x 64). rfft-1024 via complex FFT-512 (radix 8x8x8), untangle
// fused into per-patch accumulation, segmented shfl reduce, 99-float partial
// written to g_fpart. Short blocks = R8-style high-issue scheduling.
// ---------------------------------------------------------------------------
__global__ __launch_bounds__(192, 5) void frame_kernel(
    const float* __restrict__ xs, const float* __restrict__ xt,
    const float* __restrict__ xg)
{
    const int tid = threadIdx.x;
    const int grp = tid / 64;          // which signal
    const int t64 = tid & 63;
    const int blk = blockIdx.x;        // 16400 = BATCH*NT
    const int b   = blk / NT;
    const int t   = blk - b * NT;

    __shared__ float2 SH[3][2][576];   // per-signal ping-pong FFT slabs
    __shared__ float  pacc[NFP * 3];

    const float* x = (grp == 0 ? xs : (grp == 1 ? xt : xg)) + (size_t)b * LEN;
    float2* buf0 = SH[grp][0];
    float2* buf1 = SH[grp][1];
    const int n1A = t64 >> 3;
    const int n0A = t64 & 7;
    const int F = t * HOP - 512;

    // ---- load z[n] = x[2n] + i x[2n+1], n = t64 + 64*k ----
    float2 a0, a1, a2, a3, a4, a5, a6, a7;
    if (F >= 0 && F + NFFT <= LEN) {
        const float2* x2 = (const float2*)(x + F);
        a0 = x2[t64];       a1 = x2[t64 + 64];  a2 = x2[t64 + 128]; a3 = x2[t64 + 192];
        a4 = x2[t64 + 256]; a5 = x2[t64 + 320]; a6 = x2[t64 + 384]; a7 = x2[t64 + 448];
    } else {
#define LOADR(dst, K) { int g = F + 2 * (t64 + 64 * (K));                          \
        int i0 = min(abs(g), REFL2 - g); int i1 = min(abs(g + 1), REFL2 - g - 1);  \
        dst = make_float2(x[i0], x[i1]); }
        LOADR(a0, 0) LOADR(a1, 1) LOADR(a2, 2) LOADR(a3, 3)
        LOADR(a4, 4) LOADR(a5, 5) LOADR(a6, 6) LOADR(a7, 7)
#undef LOADR
    }

    // ---- step A: FFT8 over n2; twiddle from global tables (L1-resident) ----
    fft8(a0, a1, a2, a3, a4, a5, a6, a7);
    a1 = cmul(a1, g_twa[n1A * 8 + 1]);
    a2 = cmul(a2, g_twa[n1A * 8 + 2]);
    a3 = cmul(a3, g_twa[n1A * 8 + 3]);
    a4 = cmul(a4, g_twa[n1A * 8 + 4]);
    a5 = cmul(a5, g_twa[n1A * 8 + 5]);
    a6 = cmul(a6, g_twa[n1A * 8 + 6]);
    a7 = cmul(a7, g_twa[n1A * 8 + 7]);
    {
        const int wi = n1A * 9 + n0A;
        buf0[wi]       = a0; buf0[wi + 72]  = a1; buf0[wi + 144] = a2; buf0[wi + 216] = a3;
        buf0[wi + 288] = a4; buf0[wi + 360] = a5; buf0[wi + 432] = a6; buf0[wi + 504] = a7;
    }
    GBAR(grp);

    // ---- step B: gather over n1; FFT8; twiddle ----
    {
        const int n0b = t64 & 7;
        const int k0  = t64 >> 3;
        const int rb  = k0 * 72 + n0b;
        float2 b0 = buf0[rb];      float2 b1 = buf0[rb + 9];  float2 b2 = buf0[rb + 18];
        float2 b3 = buf0[rb + 27]; float2 b4 = buf0[rb + 36]; float2 b5 = buf0[rb + 45];
        float2 b6 = buf0[rb + 54]; float2 b7 = buf0[rb + 63];
        fft8(b0, b1, b2, b3, b4, b5, b6, b7);
        b0 = cmul(b0, g_twb[t64]);
        b1 = cmul(b1, g_twb[64  + t64]);
        b2 = cmul(b2, g_twb[128 + t64]);
        b3 = cmul(b3, g_twb[192 + t64]);
        b4 = cmul(b4, g_twb[256 + t64]);
        b5 = cmul(b5, g_twb[320 + t64]);
        b6 = cmul(b6, g_twb[384 + t64]);
        b7 = cmul(b7, g_twb[448 + t64]);
        const int wb = k0 * 9 + n0b;
        buf1[wb]       = b0; buf1[wb + 72]  = b1; buf1[wb + 144] = b2; buf1[wb + 216] = b3;
        buf1[wb + 288] = b4; buf1[wb + 360] = b5; buf1[wb + 432] = b6; buf1[wb + 504] = b7;
    }
    GBAR(grp);

    // ---- step C: gather over n0; FFT8 -> Z; publish Z[j] at buf0[j] ----
    {
        const int k0c = t64 & 7;
        const int k1  = t64 >> 3;
        const int rc  = k1 * 72 + k0c * 9;
        float2 c0 = buf1[rc];     float2 c1 = buf1[rc + 1]; float2 c2 = buf1[rc + 2];
        float2 c3 = buf1[rc + 3]; float2 c4 = buf1[rc + 4]; float2 c5 = buf1[rc + 5];
        float2 c6 = buf1[rc + 6]; float2 c7 = buf1[rc + 7];
        fft8(c0, c1, c2, c3, c4, c5, c6, c7);
        buf0[t64]       = c0; buf0[t64 + 64]  = c1; buf0[t64 + 128] = c2; buf0[t64 + 192] = c3;
        buf0[t64 + 256] = c4; buf0[t64 + 320] = c5; buf0[t64 + 384] = c6; buf0[t64 + 448] = c7;
    }
    __syncthreads();   // all three signals' Z ready

    // ---- fused untangle + per-patch stats; 3 freq bands per thread ----
    float st[9];       // [band][stat]: S, T, P
#pragma unroll
    for (int bd = 0; bd < 3; bd++) {
        const int f = tid + 192 * bd;
        float m[3];
        if (f < 512) {
            float2 w = g_twu[f];
            const int fm = (512 - f) & 511;
#pragma unroll
            for (int sig = 0; sig < 3; sig++) {
                float2 Zj = SH[sig][0][f];
                float2 Zm = SH[sig][0][fm];
                float ex = 0.5f * (Zj.x + Zm.x), ey = 0.5f * (Zj.y - Zm.y);
                float dx = 0.5f * (Zj.x - Zm.x), dy = 0.5f * (Zj.y + Zm.y);
                float ox = dy, oy = -dx;
                float xr_ = ex + (w.x * ox - w.y * oy);
                float xi_ = ey + (w.x * oy + w.y * ox);
                m[sig] = fmaxf(sqrtf(xr_ * xr_ + xi_ * xi_), 1e-8f);
            }
        } else if (f == 512) {
#pragma unroll
            for (int sig = 0; sig < 3; sig++) {
                float2 Z0 = SH[sig][0][0];
                m[sig] = fmaxf(fabsf(Z0.x - Z0.y), 1e-8f);
            }
        } else {
            m[0] = m[1] = m[2] = 0.f;
        }
        if (f <= 512) {
            st[bd * 3 + 0] = fabsf(m[0] - m[2]);
            st[bd * 3 + 1] = fabsf(m[1] - m[2]);
            float d = m[0] - m[1];
            st[bd * 3 + 2] = d * d;
        } else {
            st[bd * 3 + 0] = 0.f; st[bd * 3 + 1] = 0.f; st[bd * 3 + 2] = 0.f;
        }
    }

    // ---- segmented (16-lane) reduction; lanes 0,16 hold patch sums ----
#pragma unroll
    for (int k = 0; k < 9; k++) {
#pragma unroll
        for (int o = 8; o; o >>= 1)
            st[k] += __shfl_down_sync(0xffffffffu, st[k], o);
    }
    const int lane = tid & 31;
    if ((lane & 15) == 0) {
        const int segf = tid & ~15;          // segment's base f for band 0
#pragma unroll
        for (int bd = 0; bd < 3; bd++) {
            int p = (segf + 192 * bd) >> 4;
            if (p < NFP) {
                pacc[p * 3 + 0] = st[bd * 3 + 0];
                pacc[p * 3 + 1] = st[bd * 3 + 1];
                pacc[p * 3 + 2] = st[bd * 3 + 2];
            }
        }
    }
    __syncthreads();

    if (tid < NFP * 3)
        g_fpart[(size_t)blk * (NFP * 3) + tid] = pacc[tid];
}

// ---------------------------------------------------------------------------
// Kernel 3: per-batch top-k selection (exact, index-order tie-break) + stats.
// Folds the 16-frame partial-sum reduction into the load loop.
// ---------------------------------------------------------------------------
__device__ __forceinline__ int bredI(int v, int* scr) {
    const int tid = threadIdx.x;
#pragma unroll
    for (int o = 16; o; o >>= 1) v += __shfl_down_sync(0xffffffffu, v, o);
    __syncthreads();
    if ((tid & 31) == 0) scr[tid >> 5] = v;
    __syncthreads();
    int r = 0;
#pragma unroll
    for (int j = 0; j < 8; j++) r += scr[j];
    return r;
}
__device__ __forceinline__ float bredF(float v, float* scr) {
    const int tid = threadIdx.x;
#pragma unroll
    for (int o = 16; o; o >>= 1) v += __shfl_down_sync(0xffffffffu, v, o);
    __syncthreads();
    if ((tid & 31) == 0) scr[tid >> 5] = v;
    __syncthreads();
    float r = 0.f;
#pragma unroll
    for (int j = 0; j < 8; j++) r += scr[j];
    return r;
}

__global__ __launch_bounds__(256) void select_kernel() {
    const int b = blockIdx.x, tid = threadIdx.x;
    __shared__ unsigned su[NP];
    __shared__ float    spl[NP];
    __shared__ int      eqidx[NP];
    __shared__ int      iscr[8];
    __shared__ float    fscr[8];
    __shared__ int      eqc;

    float ksum = 0.f; int pcnt = 0;
    for (int i = tid; i < NP; i += 256) {
        int fp = i / NTP, tp = i - fp * NTP;       // patch order p = fp*NTP+tp
        int tbase = tp * 16;
        int jmax = min(16, NT - tbase);
        const float* pp = g_fpart + ((size_t)(b * NT + tbase)) * (NFP * 3) + fp * 3;
        float S = 0.f, T = 0.f, P = 0.f;
        for (int j = 0; j < jmax; j++) {
            S += pp[0]; T += pp[1]; P += pp[2];
            pp += NFP * 3;
        }
        float kv = (S - T) * (1.0f / 256.0f);
        spl[i] = P * (1.0f / 256.0f);
        unsigned bits = __float_as_uint(kv);
        su[i] = (bits & 0x80000000u) ? ~bits : (bits | 0x80000000u); // order-preserving
        ksum += kv;
        pcnt += (kv > 0.f) ? 1 : 0;
    }
    if (tid == 0) eqc = 0;
    __syncthreads();

    ksum = bredF(ksum, fscr);
    pcnt = bredI(pcnt, iscr);

    // binary search for k-th largest key: max v with count(u >= v) >= KSEL
    unsigned long long lo = 0ull, hi = 0xFFFFFFFFull;
    while (lo < hi) {
        unsigned long long mid = lo + ((hi - lo + 1ull) >> 1);
        int c = 0;
        for (int i = tid; i < NP; i += 256)
            c += ((unsigned long long)su[i] >= mid) ? 1 : 0;
        c = bredI(c, iscr);
        if (c >= KSEL) lo = mid; else hi = mid - 1ull;
    }
    const unsigned v = (unsigned)lo;

    int cgt = 0; float ssel = 0.f;
    for (int i = tid; i < NP; i += 256) {
        unsigned u = su[i];
        if (u > v) { cgt++; ssel += spl[i]; }
        else if (u == v) { int pos = atomicAdd(&eqc, 1); eqidx[pos] = i; }
    }
    cgt  = bredI(cgt, iscr);
    ssel = bredF(ssel, fscr);
    __syncthreads();

    if (tid == 0) {
        int need = KSEL - cgt;         // >= 1 by construction
        int ce   = eqc;
        float extra = 0.f;
        if (need >= ce) {
            for (int j = 0; j < ce; j++) extra += spl[eqidx[j]];
        } else {
            int last = -1;
            for (int t2 = 0; t2 < need; t2++) {
                int mn = 0x7fffffff;
                for (int j = 0; j < ce; j++) {
                    int ix = eqidx[j];
                    if (ix > last && ix < mn) mn = ix;
                }
                extra += spl[mn];
                last = mn;
            }
        }
        g_bsel[b] = (ssel + extra) * (1.0f / (float)KSEL);
        g_bkgs[b] = ksum;
        g_bpos[b] = pcnt;
    }
}

// ---------------------------------------------------------------------------
// Kernel 4: finalize the 4 scalars
// ---------------------------------------------------------------------------
__global__ void final_kernel(float* __restrict__ out) {
    const int t = threadIdx.x;
    float s  = (t < BATCH) ? g_bsel[t] : 0.f;
    float kg = (t < BATCH) ? g_bkgs[t] : 0.f;
    float pc = (t < BATCH) ? (float)g_bpos[t] : 0.f;
#pragma unroll
    for (int o = 16; o; o >>= 1) {
        s  += __shfl_down_sync(0xffffffffu, s,  o);
        kg += __shfl_down_sync(0xffffffffu, kg, o);
        pc += __shfl_down_sync(0xffffffffu, pc, o);
    }
    if (t == 0) {
        out[0] = s * (1.0f / (float)BATCH);                      // loss
        out[1] = (float)KSEL / (float)NP;                        // sel_ratio
        out[2] = kg / (float)(BATCH * NP);                       // kgs_mean
        out[3] = pc / (float)(BATCH * NP);                       // kgs_pos_ratio
    }
}

extern "C" void kernel_launch(void* const* d_in, const int* in_sizes, int n_in,
                              void* d_out, int out_size) {
    const float* xs = (const float*)d_in[0];
    const float* xt = (const float*)d_in[1];
    const float* xg = (const float*)d_in[2];
    float* out = (float*)d_out;

    init_tw<<<9, 128>>>();
    frame_kernel<<<NFRM, 192>>>(xs, xt, xg);   // 16400 one-frame blocks
    select_kernel<<<BATCH, 256>>>();
    final_kernel<<<1, 32>>>(out);
}

// round 14
// speedup vs baseline: 1.2334x; 1.2334x over previous
#include <cuda_runtime.h>
#include <cuda_bf16.h>
#include <math.h>

// Problem constants (fixed by setup_inputs)
#define BATCH   16
#define LEN     262144
#define NFFT    1024
#define HOP     256
#define NT      1025          // frames
#define NF      513           // rfft bins (valid)
#define NTP     65            // time patches
#define NFP     33            // freq patches
#define NP      2145          // patches per batch (33*65)
#define KSEL    643           // int(2145*0.3)
#define REFL2   (2*LEN - 2)   // 524286

// Scratch (static device memory; no allocation allowed)
__device__ float g_part[(size_t)BATCH * NTP * NFP * 3];  // [pt=b*NTP+tp][fp][3]
__device__ float g_bsel[BATCH];
__device__ float g_bkgs[BATCH];
__device__ int   g_bpos[BATCH];
__device__ float2 g_twa[64];     // W64^{n1*c}
__device__ float2 g_twb[512];    // [c*64+t] = W512^{n0*(k0+8c)}
__device__ float2 g_twu[512];    // e^{-i pi j/512}

// ---- complex helpers (float2) ----
__device__ __forceinline__ float2 cadd(float2 a, float2 b) { return make_float2(a.x + b.x, a.y + b.y); }
__device__ __forceinline__ float2 csub(float2 a, float2 b) { return make_float2(a.x - b.x, a.y - b.y); }
__device__ __forceinline__ float2 cmul(float2 a, float2 b) {
    return make_float2(a.x * b.x - a.y * b.y, a.x * b.y + a.y * b.x);
}
__device__ __forceinline__ float2 cmni(float2 a) { return make_float2(a.y, -a.x); }  // * (-i)

// FFT-8, natural-order in/out, straight-line on named registers.
__device__ __forceinline__ void fft8(float2& a0, float2& a1, float2& a2, float2& a3,
                                     float2& a4, float2& a5, float2& a6, float2& a7) {
    float2 ee0 = cadd(a0, a4), ee1 = csub(a0, a4);
    float2 oo0 = cadd(a2, a6), oo1 = csub(a2, a6);
    float2 E0 = cadd(ee0, oo0), E2 = csub(ee0, oo0);
    float2 tm = cmni(oo1);
    float2 E1 = cadd(ee1, tm), E3 = csub(ee1, tm);
    float2 fe0 = cadd(a1, a5), fe1 = csub(a1, a5);
    float2 fo0 = cadd(a3, a7), fo1 = csub(a3, a7);
    float2 O0 = cadd(fe0, fo0), O2 = csub(fe0, fo0);
    float2 um = cmni(fo1);
    float2 O1 = cadd(fe1, um), O3 = csub(fe1, um);
    const float s = 0.70710678118654752f;
    float2 w1o = make_float2(s * (O1.x + O1.y), s * (O1.y - O1.x));   // w8 * O1
    float2 w3o = make_float2(s * (O3.y - O3.x), -s * (O3.x + O3.y));  // w8^3 * O3
    float2 m2  = cmni(O2);
    a0 = cadd(E0, O0);  a4 = csub(E0, O0);
    a1 = cadd(E1, w1o); a5 = csub(E1, w1o);
    a2 = cadd(E2, m2);  a6 = csub(E2, m2);
    a3 = cadd(E3, w3o); a7 = csub(E3, w3o);
}

// group barrier: 64 threads (2 warps) of signal-group grp, named barrier 1..3
#define GBAR(grp) asm volatile("bar.sync %0, 64;" :: "r"((grp) + 1) : "memory")

// ---------------------------------------------------------------------------
// Init: build twiddle tables ONCE per launch (idempotent, deterministic).
// ---------------------------------------------------------------------------
__global__ void init_tw() {
    int idx = blockIdx.x * 128 + threadIdx.x;
    float sn, cs;
    if (idx < 64) {
        int n1 = idx >> 3, c = idx & 7;
        sincospif(-(float)(n1 * c) * (1.0f / 32.0f), &sn, &cs);
        g_twa[idx] = make_float2(cs, sn);
    } else if (idx < 576) {
        int e = idx - 64; int c = e >> 6; int t_ = e & 63;
        int n0b = t_ & 7, k0 = t_ >> 3;
        sincospif(-(float)(n0b * (k0 + 8 * c)) * (1.0f / 256.0f), &sn, &cs);
        g_twb[e] = make_float2(cs, sn);
    } else if (idx < 1088) {
        int j = idx - 576;
        sincospif(-(float)j * (1.0f / 512.0f), &sn, &cs);
        g_twu[j] = make_float2(cs, sn);
    }
}

// ---------------------------------------------------------------------------
// Fused STFT + patch kernel (R9 champion structure, 4 barriers/frame).
// Block = (b,tp); 192 threads = 3 signal-groups x 64; 16 serial frames.
// Per frame: FFT-512 (radix 8x8x8, 2 group barriers), publish Z, block sync,
// accumulate with untangle FUSED (each thread: 3 bands x 3 signals inline),
// block sync. Fold once per block; partials to g_part (deterministic).
// ---------------------------------------------------------------------------
__global__ __launch_bounds__(192, 5) void fused_kernel(
    const float* __restrict__ xs, const float* __restrict__ xt,
    const float* __restrict__ xg)
{
    const int tid = threadIdx.x;
    const int grp = tid / 64;          // which signal
    const int t64 = tid & 63;
    const int pt  = blockIdx.x;        // 1040 = BATCH*NTP
    const int b   = pt / NTP;
    const int tp  = pt - b * NTP;

    __shared__ float2 SH[3][2][576];   // per-signal ping-pong FFT slabs
    __shared__ float  pacc[NFP * 3];

    if (tid < NFP * 3) pacc[tid] = 0.f;

    const float* x = (grp == 0 ? xs : (grp == 1 ? xt : xg)) + (size_t)b * LEN;
    float2* buf0 = SH[grp][0];
    float2* buf1 = SH[grp][1];
    const int n1A = t64 >> 3;
    const int n0A = t64 & 7;

    // per-thread patch accumulators (f = tid, tid+192, tid+384)
    float aS0 = 0.f, aT0 = 0.f, aP0 = 0.f;
    float aS1 = 0.f, aT1 = 0.f, aP1 = 0.f;
    float aS2 = 0.f, aT2 = 0.f, aP2 = 0.f;

    for (int it = 0; it < 16; it++) {
        const int t = tp * 16 + it;
        if (t >= NT) break;                      // uniform across block
        const int F = t * HOP - 512;

        // ---- load z[n] = x[2n] + i x[2n+1], n = t64 + 64*k ----
        float2 a0, a1, a2, a3, a4, a5, a6, a7;
        if (F >= 0 && F + NFFT <= LEN) {
            const float2* x2 = (const float2*)(x + F);
            a0 = x2[t64];       a1 = x2[t64 + 64];  a2 = x2[t64 + 128]; a3 = x2[t64 + 192];
            a4 = x2[t64 + 256]; a5 = x2[t64 + 320]; a6 = x2[t64 + 384]; a7 = x2[t64 + 448];
        } else {
#define LOADR(dst, K) { int g = F + 2 * (t64 + 64 * (K));                          \
            int i0 = min(abs(g), REFL2 - g); int i1 = min(abs(g + 1), REFL2 - g - 1); \
            dst = make_float2(x[i0], x[i1]); }
            LOADR(a0, 0) LOADR(a1, 1) LOADR(a2, 2) LOADR(a3, 3)
            LOADR(a4, 4) LOADR(a5, 5) LOADR(a6, 6) LOADR(a7, 7)
#undef LOADR
        }

        // ---- step A: FFT8 over n2; twiddle from global tables (L1) ----
        fft8(a0, a1, a2, a3, a4, a5, a6, a7);
        a1 = cmul(a1, g_twa[n1A * 8 + 1]);
        a2 = cmul(a2, g_twa[n1A * 8 + 2]);
        a3 = cmul(a3, g_twa[n1A * 8 + 3]);
        a4 = cmul(a4, g_twa[n1A * 8 + 4]);
        a5 = cmul(a5, g_twa[n1A * 8 + 5]);
        a6 = cmul(a6, g_twa[n1A * 8 + 6]);
        a7 = cmul(a7, g_twa[n1A * 8 + 7]);
        {
            const int wi = n1A * 9 + n0A;
            buf0[wi]       = a0; buf0[wi + 72]  = a1; buf0[wi + 144] = a2; buf0[wi + 216] = a3;
            buf0[wi + 288] = a4; buf0[wi + 360] = a5; buf0[wi + 432] = a6; buf0[wi + 504] = a7;
        }
        GBAR(grp);

        // ---- step B: gather over n1; FFT8; twiddle; write buf1 ----
        {
            const int n0b = t64 & 7;
            const int k0  = t64 >> 3;
            const int rb  = k0 * 72 + n0b;
            float2 b0 = buf0[rb];      float2 b1 = buf0[rb + 9];  float2 b2 = buf0[rb + 18];
            float2 b3 = buf0[rb + 27]; float2 b4 = buf0[rb + 36]; float2 b5 = buf0[rb + 45];
            float2 b6 = buf0[rb + 54]; float2 b7 = buf0[rb + 63];
            fft8(b0, b1, b2, b3, b4, b5, b6, b7);
            b0 = cmul(b0, g_twb[t64]);
            b1 = cmul(b1, g_twb[64  + t64]);
            b2 = cmul(b2, g_twb[128 + t64]);
            b3 = cmul(b3, g_twb[192 + t64]);
            b4 = cmul(b4, g_twb[256 + t64]);
            b5 = cmul(b5, g_twb[320 + t64]);
            b6 = cmul(b6, g_twb[384 + t64]);
            b7 = cmul(b7, g_twb[448 + t64]);
            const int wb = k0 * 9 + n0b;
            buf1[wb]       = b0; buf1[wb + 72]  = b1; buf1[wb + 144] = b2; buf1[wb + 216] = b3;
            buf1[wb + 288] = b4; buf1[wb + 360] = b5; buf1[wb + 432] = b6; buf1[wb + 504] = b7;
        }
        GBAR(grp);

        // ---- step C: gather over n0; FFT8 -> Z; publish Z[j] at buf0[j] ----
        {
            const int k0c = t64 & 7;
            const int k1  = t64 >> 3;
            const int rc  = k1 * 72 + k0c * 9;
            float2 c0 = buf1[rc];     float2 c1 = buf1[rc + 1]; float2 c2 = buf1[rc + 2];
            float2 c3 = buf1[rc + 3]; float2 c4 = buf1[rc + 4]; float2 c5 = buf1[rc + 5];
            float2 c6 = buf1[rc + 6]; float2 c7 = buf1[rc + 7];
            fft8(c0, c1, c2, c3, c4, c5, c6, c7);
            buf0[t64]       = c0; buf0[t64 + 64]  = c1; buf0[t64 + 128] = c2; buf0[t64 + 192] = c3;
            buf0[t64 + 256] = c4; buf0[t64 + 320] = c5; buf0[t64 + 384] = c6; buf0[t64 + 448] = c7;
        }
        __syncthreads();   // all three signals' Z published

        // ---- fused untangle + accumulate: 3 bands x 3 signals inline ----
#pragma unroll
        for (int bd = 0; bd < 3; bd++) {
            const int f = tid + 192 * bd;
            if (f <= 512) {
                float m[3];
                if (f < 512) {
                    float2 w = g_twu[f];
                    const int fm = (512 - f) & 511;
#pragma unroll
                    for (int sig = 0; sig < 3; sig++) {
                        float2 Zj = SH[sig][0][f];
                        float2 Zm = SH[sig][0][fm];
                        float ex = 0.5f * (Zj.x + Zm.x), ey = 0.5f * (Zj.y - Zm.y);
                        float dx = 0.5f * (Zj.x - Zm.x), dy = 0.5f * (Zj.y + Zm.y);
                        float ox = dy, oy = -dx;
                        float xr_ = ex + (w.x * ox - w.y * oy);
                        float xi_ = ey + (w.x * oy + w.y * ox);
                        m[sig] = fmaxf(sqrtf(xr_ * xr_ + xi_ * xi_), 1e-8f);
                    }
                } else {   // f == 512
#pragma unroll
                    for (int sig = 0; sig < 3; sig++) {
                        float2 Z0 = SH[sig][0][0];
                        m[sig] = fmaxf(fabsf(Z0.x - Z0.y), 1e-8f);
                    }
                }
                float vS = fabsf(m[0] - m[2]);
                float vT = fabsf(m[1] - m[2]);
                float d  = m[0] - m[1];
                float vP = d * d;
                if (bd == 0)      { aS0 += vS; aT0 += vT; aP0 += vP; }
                else if (bd == 1) { aS1 += vS; aT1 += vT; aP1 += vP; }
                else              { aS2 += vS; aT2 += vT; aP2 += vP; }
            }
        }
        __syncthreads();   // protect buf0 before next frame's A-write
    }

    // ---- fold per-thread accumulators into per-f-patch sums ----
    {
        int p0 = tid >> 4;                       // f = tid
        atomicAdd(&pacc[p0 * 3 + 0], aS0);
        atomicAdd(&pacc[p0 * 3 + 1], aT0);
        atomicAdd(&pacc[p0 * 3 + 2], aP0);
        int p1 = (tid + 192) >> 4;               // f = tid+192
        atomicAdd(&pacc[p1 * 3 + 0], aS1);
        atomicAdd(&pacc[p1 * 3 + 1], aT1);
        atomicAdd(&pacc[p1 * 3 + 2], aP1);
        if (tid + 384 <= 512) {                  // f = tid+384
            int p2 = (tid + 384) >> 4;
            atomicAdd(&pacc[p2 * 3 + 0], aS2);
            atomicAdd(&pacc[p2 * 3 + 1], aT2);
            atomicAdd(&pacc[p2 * 3 + 2], aP2);
        }
    }
    __syncthreads();

    if (tid < NFP * 3)
        g_part[(size_t)pt * (NFP * 3) + tid] = pacc[tid];
}

// ---------------------------------------------------------------------------
// Kernel 3: per-batch top-k selection (exact, index-order tie-break) + stats
// ---------------------------------------------------------------------------
__device__ __forceinline__ int bredI(int v, int* scr) {
    const int tid = threadIdx.x;
#pragma unroll
    for (int o = 16; o; o >>= 1) v += __shfl_down_sync(0xffffffffu, v, o);
    __syncthreads();
    if ((tid & 31) == 0) scr[tid >> 5] = v;
    __syncthreads();
    int r = 0;
#pragma unroll
    for (int j = 0; j < 8; j++) r += scr[j];
    return r;
}
__device__ __forceinline__ float bredF(float v, float* scr) {
    const int tid = threadIdx.x;
#pragma unroll
    for (int o = 16; o; o >>= 1) v += __shfl_down_sync(0xffffffffu, v, o);
    __syncthreads();
    if ((tid & 31) == 0) scr[tid >> 5] = v;
    __syncthreads();
    float r = 0.f;
#pragma unroll
    for (int j = 0; j < 8; j++) r += scr[j];
    return r;
}

__global__ __launch_bounds__(256) void select_kernel() {
    const int b = blockIdx.x, tid = threadIdx.x;
    __shared__ unsigned su[NP];
    __shared__ float    spl[NP];
    __shared__ int      eqidx[NP];
    __shared__ int      iscr[8];
    __shared__ float    fscr[8];
    __shared__ int      eqc;

    float ksum = 0.f; int pcnt = 0;
    for (int i = tid; i < NP; i += 256) {
        int fp = i / NTP, tp = i - fp * NTP;       // patch order p = fp*NTP+tp
        const float* pp = g_part + ((size_t)(b * NTP + tp) * NFP + fp) * 3;
        float kv = (pp[0] - pp[1]) * (1.0f / 256.0f);
        spl[i] = pp[2] * (1.0f / 256.0f);
        unsigned bits = __float_as_uint(kv);
        su[i] = (bits & 0x80000000u) ? ~bits : (bits | 0x80000000u); // order-preserving
        ksum += kv;
        pcnt += (kv > 0.f) ? 1 : 0;
    }
    if (tid == 0) eqc = 0;
    __syncthreads();

    ksum = bredF(ksum, fscr);
    pcnt = bredI(pcnt, iscr);

    // binary search for k-th largest key: max v with count(u >= v) >= KSEL
    unsigned long long lo = 0ull, hi = 0xFFFFFFFFull;
    while (lo < hi) {
        unsigned long long mid = lo + ((hi - lo + 1ull) >> 1);
        int c = 0;
        for (int i = tid; i < NP; i += 256)
            c += ((unsigned long long)su[i] >= mid) ? 1 : 0;
        c = bredI(c, iscr);
        if (c >= KSEL) lo = mid; else hi = mid - 1ull;
    }
    const unsigned v = (unsigned)lo;

    int cgt = 0; float ssel = 0.f;
    for (int i = tid; i < NP; i += 256) {
        unsigned u = su[i];
        if (u > v) { cgt++; ssel += spl[i]; }
        else if (u == v) { int pos = atomicAdd(&eqc, 1); eqidx[pos] = i; }
    }
    cgt  = bredI(cgt, iscr);
    ssel = bredF(ssel, fscr);
    __syncthreads();

    if (tid == 0) {
        int need = KSEL - cgt;         // >= 1 by construction
        int ce   = eqc;
        float extra = 0.f;
        if (need >= ce) {
            for (int j = 0; j < ce; j++) extra += spl[eqidx[j]];
        } else {
            int last = -1;
            for (int t2 = 0; t2 < need; t2++) {
                int mn = 0x7fffffff;
                for (int j = 0; j < ce; j++) {
                    int ix = eqidx[j];
                    if (ix > last && ix < mn) mn = ix;
                }
                extra += spl[mn];
                last = mn;
            }
        }
        g_bsel[b] = (ssel + extra) * (1.0f / (float)KSEL);
        g_bkgs[b] = ksum;
        g_bpos[b] = pcnt;
    }
}

// ---------------------------------------------------------------------------
// Kernel 4: finalize the 4 scalars
// ---------------------------------------------------------------------------
__global__ void final_kernel(float* __restrict__ out) {
    const int t = threadIdx.x;
    float s  = (t < BATCH) ? g_bsel[t] : 0.f;
    float kg = (t < BATCH) ? g_bkgs[t] : 0.f;
    float pc = (t < BATCH) ? (float)g_bpos[t] : 0.f;
#pragma unroll
    for (int o = 16; o; o >>= 1) {
        s  += __shfl_down_sync(0xffffffffu, s,  o);
        kg += __shfl_down_sync(0xffffffffu, kg, o);
        pc += __shfl_down_sync(0xffffffffu, pc, o);
    }
    if (t == 0) {
        out[0] = s * (1.0f / (float)BATCH);                      // loss
        out[1] = (float)KSEL / (float)NP;                        // sel_ratio
        out[2] = kg / (float)(BATCH * NP);                       // kgs_mean
        out[3] = pc / (float)(BATCH * NP);                       // kgs_pos_ratio
    }
}

extern "C" void kernel_launch(void* const* d_in, const int* in_sizes, int n_in,
                              void* d_out, int out_size) {
    const float* xs = (const float*)d_in[0];
    const float* xt = (const float*)d_in[1];
    const float* xg = (const float*)d_in[2];
    float* out = (float*)d_out;

    init_tw<<<9, 128>>>();
    fused_kernel<<<BATCH * NTP, 192>>>(xs, xt, xg);   // 1040 blocks
    select_kernel<<<BATCH, 256>>>();
    final_kernel<<<1, 32>>>(out);
}

// round 15
// speedup vs baseline: 1.3016x; 1.0553x over previous
#include <cuda_runtime.h>
#include <cuda_bf16.h>
#include <math.h>

// Problem constants (fixed by setup_inputs)
#define BATCH   16
#define LEN     262144
#define NFFT    1024
#define HOP     256
#define NT      1025          // frames
#define NF      513           // rfft bins (valid)
#define NTP     65            // time patches
#define NFP     33            // freq patches
#define NP      2145          // patches per batch (33*65)
#define KSEL    643           // int(2145*0.3)
#define REFL2   (2*LEN - 2)   // 524286

// Scratch (static device memory; no allocation allowed)
__device__ float g_part[(size_t)BATCH * NTP * NFP * 3];  // [pt=b*NTP+tp][fp][3]
__device__ float g_bsel[BATCH];
__device__ float g_bkgs[BATCH];
__device__ int   g_bpos[BATCH];
__device__ int   g_done;

// ---- complex helpers (float2) ----
__device__ __forceinline__ float2 cadd(float2 a, float2 b) { return make_float2(a.x + b.x, a.y + b.y); }
__device__ __forceinline__ float2 csub(float2 a, float2 b) { return make_float2(a.x - b.x, a.y - b.y); }
__device__ __forceinline__ float2 cmul(float2 a, float2 b) {
    return make_float2(a.x * b.x - a.y * b.y, a.x * b.y + a.y * b.x);
}
__device__ __forceinline__ float2 cmni(float2 a) { return make_float2(a.y, -a.x); }  // * (-i)

// FFT-8, natural-order in/out, straight-line on named registers.
__device__ __forceinline__ void fft8(float2& a0, float2& a1, float2& a2, float2& a3,
                                     float2& a4, float2& a5, float2& a6, float2& a7) {
    float2 ee0 = cadd(a0, a4), ee1 = csub(a0, a4);
    float2 oo0 = cadd(a2, a6), oo1 = csub(a2, a6);
    float2 E0 = cadd(ee0, oo0), E2 = csub(ee0, oo0);
    float2 tm = cmni(oo1);
    float2 E1 = cadd(ee1, tm), E3 = csub(ee1, tm);
    float2 fe0 = cadd(a1, a5), fe1 = csub(a1, a5);
    float2 fo0 = cadd(a3, a7), fo1 = csub(a3, a7);
    float2 O0 = cadd(fe0, fo0), O2 = csub(fe0, fo0);
    float2 um = cmni(fo1);
    float2 O1 = cadd(fe1, um), O3 = csub(fe1, um);
    const float s = 0.70710678118654752f;
    float2 w1o = make_float2(s * (O1.x + O1.y), s * (O1.y - O1.x));   // w8 * O1
    float2 w3o = make_float2(s * (O3.y - O3.x), -s * (O3.x + O3.y));  // w8^3 * O3
    float2 m2  = cmni(O2);
    a0 = cadd(E0, O0);  a4 = csub(E0, O0);
    a1 = cadd(E1, w1o); a5 = csub(E1, w1o);
    a2 = cadd(E2, m2);  a6 = csub(E2, m2);
    a3 = cadd(E3, w3o); a7 = csub(E3, w3o);
}

// group barrier: 64 threads (2 warps) of signal-group grp, named barrier 1..3
#define GBAR(grp) asm volatile("bar.sync %0, 64;" :: "r"((grp) + 1) : "memory")

// Load one frame's packed complex input (z[n] = x[2n] + i x[2n+1]).
__device__ __forceinline__ void load_frame(
    const float* __restrict__ x, int F, int t64,
    float2& a0, float2& a1, float2& a2, float2& a3,
    float2& a4, float2& a5, float2& a6, float2& a7)
{
    if (F >= 0 && F + NFFT <= LEN) {
        const float2* x2 = (const float2*)(x + F);
        a0 = x2[t64];       a1 = x2[t64 + 64];  a2 = x2[t64 + 128]; a3 = x2[t64 + 192];
        a4 = x2[t64 + 256]; a5 = x2[t64 + 320]; a6 = x2[t64 + 384]; a7 = x2[t64 + 448];
    } else {
#define LOADR(dst, K) { int g = F + 2 * (t64 + 64 * (K));                          \
        int i0 = min(abs(g), REFL2 - g); int i1 = min(abs(g + 1), REFL2 - g - 1);  \
        dst = make_float2(x[i0], x[i1]); }
        LOADR(a0, 0) LOADR(a1, 1) LOADR(a2, 2) LOADR(a3, 3)
        LOADR(a4, 4) LOADR(a5, 5) LOADR(a6, 6) LOADR(a7, 7)
#undef LOADR
    }
}

// ---------------------------------------------------------------------------
// Fused STFT + patch kernel (R9 champion + fused untangle + input prefetch).
// Block = (b,tp); 192 threads = 3 signal-groups x 64; 16 serial frames.
// Per frame: FFT-512 (2 group barriers), publish Z, PREFETCH next frame's
// input, block sync, fused untangle+accumulate, block sync.
// Twiddles in shared (built per block, as in the 120.5us champion).
// ---------------------------------------------------------------------------
__global__ __launch_bounds__(192, 4) void fused_kernel(
    const float* __restrict__ xs, const float* __restrict__ xt,
    const float* __restrict__ xg)
{
    const int tid = threadIdx.x;
    const int grp = tid / 64;          // which signal
    const int t64 = tid & 63;
    const int pt  = blockIdx.x;        // 1040 = BATCH*NTP
    const int b   = pt / NTP;
    const int tp  = pt - b * NTP;

    __shared__ float2 SH[3][2][576];   // per-signal ping-pong FFT slabs
    __shared__ float2 tw_a[64];        // W64^{n1*c}
    __shared__ float2 tw_b[512];       // [c*64+t64] = W512^{n0*(k0+8c)}
    __shared__ float2 tw_u[512];       // e^{-i pi j/512}
    __shared__ float  pacc[NFP * 3];

    // ---- build twiddle tables (once per block, R9-style) ----
    for (int idx = tid; idx < 1088; idx += 192) {
        float sn, cs;
        if (idx < 64) {
            int n1 = idx >> 3, c = idx & 7;
            sincospif(-(float)(n1 * c) * (1.0f / 32.0f), &sn, &cs);
            tw_a[idx] = make_float2(cs, sn);
        } else if (idx < 576) {
            int e = idx - 64; int c = e >> 6; int t_ = e & 63;
            int n0b = t_ & 7, k0 = t_ >> 3;
            sincospif(-(float)(n0b * (k0 + 8 * c)) * (1.0f / 256.0f), &sn, &cs);
            tw_b[e] = make_float2(cs, sn);
        } else {
            int j = idx - 576;
            sincospif(-(float)j * (1.0f / 512.0f), &sn, &cs);
            tw_u[j] = make_float2(cs, sn);
        }
    }
    if (tid < NFP * 3) pacc[tid] = 0.f;
    if (pt == 0 && tid == 0) g_done = 0;   // reset merge counter for select
    __syncthreads();

    const float* x = (grp == 0 ? xs : (grp == 1 ? xt : xg)) + (size_t)b * LEN;
    float2* buf0 = SH[grp][0];
    float2* buf1 = SH[grp][1];
    const int n1A = t64 >> 3;
    const int n0A = t64 & 7;

    // per-thread patch accumulators (f = tid, tid+192, tid+384)
    float aS0 = 0.f, aT0 = 0.f, aP0 = 0.f;
    float aS1 = 0.f, aT1 = 0.f, aP1 = 0.f;
    float aS2 = 0.f, aT2 = 0.f, aP2 = 0.f;

    const int t0  = tp * 16;
    const int nfr = min(16, NT - t0);    // 16, or 1 for tp==64

    // ---- preload frame 0 ----
    float2 a0, a1, a2, a3, a4, a5, a6, a7;
    load_frame(x, t0 * HOP - 512, t64, a0, a1, a2, a3, a4, a5, a6, a7);

    for (int it = 0; it < nfr; it++) {
        // ---- step A: FFT8 over n2; twiddle from shared table ----
        fft8(a0, a1, a2, a3, a4, a5, a6, a7);
        a1 = cmul(a1, tw_a[n1A * 8 + 1]);
        a2 = cmul(a2, tw_a[n1A * 8 + 2]);
        a3 = cmul(a3, tw_a[n1A * 8 + 3]);
        a4 = cmul(a4, tw_a[n1A * 8 + 4]);
        a5 = cmul(a5, tw_a[n1A * 8 + 5]);
        a6 = cmul(a6, tw_a[n1A * 8 + 6]);
        a7 = cmul(a7, tw_a[n1A * 8 + 7]);
        {
            const int wi = n1A * 9 + n0A;
            buf0[wi]       = a0; buf0[wi + 72]  = a1; buf0[wi + 144] = a2; buf0[wi + 216] = a3;
            buf0[wi + 288] = a4; buf0[wi + 360] = a5; buf0[wi + 432] = a6; buf0[wi + 504] = a7;
        }
        GBAR(grp);

        // ---- step B: gather over n1; FFT8; twiddle; write buf1 ----
        {
            const int n0b = t64 & 7;
            const int k0  = t64 >> 3;
            const int rb  = k0 * 72 + n0b;
            float2 b0 = buf0[rb];      float2 b1 = buf0[rb + 9];  float2 b2 = buf0[rb + 18];
            float2 b3 = buf0[rb + 27]; float2 b4 = buf0[rb + 36]; float2 b5 = buf0[rb + 45];
            float2 b6 = buf0[rb + 54]; float2 b7 = buf0[rb + 63];
            fft8(b0, b1, b2, b3, b4, b5, b6, b7);
            b0 = cmul(b0, tw_b[t64]);
            b1 = cmul(b1, tw_b[64  + t64]);
            b2 = cmul(b2, tw_b[128 + t64]);
            b3 = cmul(b3, tw_b[192 + t64]);
            b4 = cmul(b4, tw_b[256 + t64]);
            b5 = cmul(b5, tw_b[320 + t64]);
            b6 = cmul(b6, tw_b[384 + t64]);
            b7 = cmul(b7, tw_b[448 + t64]);
            const int wb = k0 * 9 + n0b;
            buf1[wb]       = b0; buf1[wb + 72]  = b1; buf1[wb + 144] = b2; buf1[wb + 216] = b3;
            buf1[wb + 288] = b4; buf1[wb + 360] = b5; buf1[wb + 432] = b6; buf1[wb + 504] = b7;
        }
        GBAR(grp);

        // ---- step C: gather over n0; FFT8 -> Z; publish Z[j] at buf0[j] ----
        {
            const int k0c = t64 & 7;
            const int k1  = t64 >> 3;
            const int rc  = k1 * 72 + k0c * 9;
            float2 c0 = buf1[rc];     float2 c1 = buf1[rc + 1]; float2 c2 = buf1[rc + 2];
            float2 c3 = buf1[rc + 3]; float2 c4 = buf1[rc + 4]; float2 c5 = buf1[rc + 5];
            float2 c6 = buf1[rc + 6]; float2 c7 = buf1[rc + 7];
            fft8(c0, c1, c2, c3, c4, c5, c6, c7);
            buf0[t64]       = c0; buf0[t64 + 64]  = c1; buf0[t64 + 128] = c2; buf0[t64 + 192] = c3;
            buf0[t64 + 256] = c4; buf0[t64 + 320] = c5; buf0[t64 + 384] = c6; buf0[t64 + 448] = c7;
        }

        // ---- PREFETCH next frame's input (overlaps barrier + accumulate) ----
        if (it + 1 < nfr)
            load_frame(x, (t0 + it + 1) * HOP - 512, t64,
                       a0, a1, a2, a3, a4, a5, a6, a7);

        __syncthreads();   // all three signals' Z published

        // ---- fused untangle + accumulate: 3 bands x 3 signals inline ----
#pragma unroll
        for (int bd = 0; bd < 3; bd++) {
            const int f = tid + 192 * bd;
            if (f <= 512) {
                float m[3];
                if (f < 512) {
                    float2 w = tw_u[f];
                    const int fm = (512 - f) & 511;
#pragma unroll
                    for (int sig = 0; sig < 3; sig++) {
                        float2 Zj = SH[sig][0][f];
                        float2 Zm = SH[sig][0][fm];
                        float ex = 0.5f * (Zj.x + Zm.x), ey = 0.5f * (Zj.y - Zm.y);
                        float dx = 0.5f * (Zj.x - Zm.x), dy = 0.5f * (Zj.y + Zm.y);
                        float ox = dy, oy = -dx;
                        float xr_ = ex + (w.x * ox - w.y * oy);
                        float xi_ = ey + (w.x * oy + w.y * ox);
                        m[sig] = fmaxf(sqrtf(xr_ * xr_ + xi_ * xi_), 1e-8f);
                    }
                } else {   // f == 512
#pragma unroll
                    for (int sig = 0; sig < 3; sig++) {
                        float2 Z0 = SH[sig][0][0];
                        m[sig] = fmaxf(fabsf(Z0.x - Z0.y), 1e-8f);
                    }
                }
                float vS = fabsf(m[0] - m[2]);
                float vT = fabsf(m[1] - m[2]);
                float d  = m[0] - m[1];
                float vP = d * d;
                if (bd == 0)      { aS0 += vS; aT0 += vT; aP0 += vP; }
                else if (bd == 1) { aS1 += vS; aT1 += vT; aP1 += vP; }
                else              { aS2 += vS; aT2 += vT; aP2 += vP; }
            }
        }
        __syncthreads();   // protect buf0 before next frame's A-write
    }

    // ---- fold per-thread accumulators into per-f-patch sums ----
    {
        int p0 = tid >> 4;                       // f = tid
        atomicAdd(&pacc[p0 * 3 + 0], aS0);
        atomicAdd(&pacc[p0 * 3 + 1], aT0);
        atomicAdd(&pacc[p0 * 3 + 2], aP0);
        int p1 = (tid + 192) >> 4;               // f = tid+192
        atomicAdd(&pacc[p1 * 3 + 0], aS1);
        atomicAdd(&pacc[p1 * 3 + 1], aT1);
        atomicAdd(&pacc[p1 * 3 + 2], aP1);
        if (tid + 384 <= 512) {                  // f = tid+384
            int p2 = (tid + 384) >> 4;
            atomicAdd(&pacc[p2 * 3 + 0], aS2);
            atomicAdd(&pacc[p2 * 3 + 1], aT2);
            atomicAdd(&pacc[p2 * 3 + 2], aP2);
        }
    }
    __syncthreads();

    if (tid < NFP * 3)
        g_part[(size_t)pt * (NFP * 3) + tid] = pacc[tid];
}

// ---------------------------------------------------------------------------
// Kernel 2: per-batch top-k selection + stats; LAST finishing block also
// computes the 4 final scalars (g_done counter, reset by fused block 0).
// ---------------------------------------------------------------------------
__device__ __forceinline__ int bredI(int v, int* scr) {
    const int tid = threadIdx.x;
#pragma unroll
    for (int o = 16; o; o >>= 1) v += __shfl_down_sync(0xffffffffu, v, o);
    __syncthreads();
    if ((tid & 31) == 0) scr[tid >> 5] = v;
    __syncthreads();
    int r = 0;
#pragma unroll
    for (int j = 0; j < 8; j++) r += scr[j];
    return r;
}
__device__ __forceinline__ float bredF(float v, float* scr) {
    const int tid = threadIdx.x;
#pragma unroll
    for (int o = 16; o; o >>= 1) v += __shfl_down_sync(0xffffffffu, v, o);
    __syncthreads();
    if ((tid & 31) == 0) scr[tid >> 5] = v;
    __syncthreads();
    float r = 0.f;
#pragma unroll
    for (int j = 0; j < 8; j++) r += scr[j];
    return r;
}

__global__ __launch_bounds__(256) void select_kernel(float* __restrict__ out) {
    const int b = blockIdx.x, tid = threadIdx.x;
    __shared__ unsigned su[NP];
    __shared__ float    spl[NP];
    __shared__ int      eqidx[NP];
    __shared__ int      iscr[8];
    __shared__ float    fscr[8];
    __shared__ int      eqc;
    __shared__ int      slast;

    float ksum = 0.f; int pcnt = 0;
    for (int i = tid; i < NP; i += 256) {
        int fp = i / NTP, tp = i - fp * NTP;       // patch order p = fp*NTP+tp
        const float* pp = g_part + ((size_t)(b * NTP + tp) * NFP + fp) * 3;
        float kv = (pp[0] - pp[1]) * (1.0f / 256.0f);
        spl[i] = pp[2] * (1.0f / 256.0f);
        unsigned bits = __float_as_uint(kv);
        su[i] = (bits & 0x80000000u) ? ~bits : (bits | 0x80000000u); // order-preserving
        ksum += kv;
        pcnt += (kv > 0.f) ? 1 : 0;
    }
    if (tid == 0) { eqc = 0; slast = 0; }
    __syncthreads();

    ksum = bredF(ksum, fscr);
    pcnt = bredI(pcnt, iscr);

    // binary search for k-th largest key: max v with count(u >= v) >= KSEL
    unsigned long long lo = 0ull, hi = 0xFFFFFFFFull;
    while (lo < hi) {
        unsigned long long mid = lo + ((hi - lo + 1ull) >> 1);
        int c = 0;
        for (int i = tid; i < NP; i += 256)
            c += ((unsigned long long)su[i] >= mid) ? 1 : 0;
        c = bredI(c, iscr);
        if (c >= KSEL) lo = mid; else hi = mid - 1ull;
    }
    const unsigned v = (unsigned)lo;

    int cgt = 0; float ssel = 0.f;
    for (int i = tid; i < NP; i += 256) {
        unsigned u = su[i];
        if (u > v) { cgt++; ssel += spl[i]; }
        else if (u == v) { int pos = atomicAdd(&eqc, 1); eqidx[pos] = i; }
    }
    cgt  = bredI(cgt, iscr);
    ssel = bredF(ssel, fscr);
    __syncthreads();

    if (tid == 0) {
        int need = KSEL - cgt;         // >= 1 by construction
        int ce   = eqc;
        float extra = 0.f;
        if (need >= ce) {
            for (int j = 0; j < ce; j++) extra += spl[eqidx[j]];
        } else {
            int last = -1;
            for (int t2 = 0; t2 < need; t2++) {
                int mn = 0x7fffffff;
                for (int j = 0; j < ce; j++) {
                    int ix = eqidx[j];
                    if (ix > last && ix < mn) mn = ix;
                }
                extra += spl[mn];
                last = mn;
            }
        }
        g_bsel[b] = (ssel + extra) * (1.0f / (float)KSEL);
        g_bkgs[b] = ksum;
        g_bpos[b] = pcnt;
        __threadfence();
        int prev = atomicAdd(&g_done, 1);
        slast = (prev == BATCH - 1) ? 1 : 0;
    }
    __syncthreads();

    // last block computes the 4 final scalars
    if (slast && tid < 32) {
        __threadfence();
        float s  = (tid < BATCH) ? g_bsel[tid] : 0.f;
        float kg = (tid < BATCH) ? g_bkgs[tid] : 0.f;
        float pc = (tid < BATCH) ? (float)g_bpos[tid] : 0.f;
#pragma unroll
        for (int o = 16; o; o >>= 1) {
            s  += __shfl_down_sync(0xffffffffu, s,  o);
            kg += __shfl_down_sync(0xffffffffu, kg, o);
            pc += __shfl_down_sync(0xffffffffu, pc, o);
        }
        if (tid == 0) {
            out[0] = s * (1.0f / (float)BATCH);                  // loss
            out[1] = (float)KSEL / (float)NP;                    // sel_ratio
            out[2] = kg / (float)(BATCH * NP);                   // kgs_mean
            out[3] = pc / (float)(BATCH * NP);                   // kgs_pos_ratio
        }
    }
}

extern "C" void kernel_launch(void* const* d_in, const int* in_sizes, int n_in,
                              void* d_out, int out_size) {
    const float* xs = (const float*)d_in[0];
    const float* xt = (const float*)d_in[1];
    const float* xg = (const float*)d_in[2];
    float* out = (float*)d_out;

    fused_kernel<<<BATCH * NTP, 192>>>(xs, xt, xg);   // 1040 blocks
    select_kernel<<<BATCH, 256>>>(out);               // final fused into select
}

// round 16
// speedup vs baseline: 1.3880x; 1.0663x over previous
#include <cuda_runtime.h>
#include <cuda_bf16.h>
#include <math.h>

// Problem constants (fixed by setup_inputs)
#define BATCH   16
#define LEN     262144
#define NFFT    1024
#define HOP     256
#define NT      1025          // frames
#define NF      513           // rfft bins (valid)
#define NTP     65            // time patches
#define NFP     33            // freq patches
#define NP      2145          // patches per batch (33*65)
#define KSEL    643           // int(2145*0.3)
#define REFL2   (2*LEN - 2)   // 524286

// Scratch (static device memory; no allocation allowed)
__device__ float g_part[(size_t)BATCH * NTP * NFP * 3];  // [pt=b*NTP+tp][fp][3]
__device__ float g_bsel[BATCH];
__device__ float g_bkgs[BATCH];
__device__ int   g_bpos[BATCH];
__device__ int   g_done;

// ---- complex helpers (float2) ----
__device__ __forceinline__ float2 cadd(float2 a, float2 b) { return make_float2(a.x + b.x, a.y + b.y); }
__device__ __forceinline__ float2 csub(float2 a, float2 b) { return make_float2(a.x - b.x, a.y - b.y); }
__device__ __forceinline__ float2 cmul(float2 a, float2 b) {
    return make_float2(a.x * b.x - a.y * b.y, a.x * b.y + a.y * b.x);
}
__device__ __forceinline__ float2 cmni(float2 a) { return make_float2(a.y, -a.x); }  // * (-i)

// FFT-8, natural-order in/out, straight-line on named registers.
__device__ __forceinline__ void fft8(float2& a0, float2& a1, float2& a2, float2& a3,
                                     float2& a4, float2& a5, float2& a6, float2& a7) {
    float2 ee0 = cadd(a0, a4), ee1 = csub(a0, a4);
    float2 oo0 = cadd(a2, a6), oo1 = csub(a2, a6);
    float2 E0 = cadd(ee0, oo0), E2 = csub(ee0, oo0);
    float2 tm = cmni(oo1);
    float2 E1 = cadd(ee1, tm), E3 = csub(ee1, tm);
    float2 fe0 = cadd(a1, a5), fe1 = csub(a1, a5);
    float2 fo0 = cadd(a3, a7), fo1 = csub(a3, a7);
    float2 O0 = cadd(fe0, fo0), O2 = csub(fe0, fo0);
    float2 um = cmni(fo1);
    float2 O1 = cadd(fe1, um), O3 = csub(fe1, um);
    const float s = 0.70710678118654752f;
    float2 w1o = make_float2(s * (O1.x + O1.y), s * (O1.y - O1.x));   // w8 * O1
    float2 w3o = make_float2(s * (O3.y - O3.x), -s * (O3.x + O3.y));  // w8^3 * O3
    float2 m2  = cmni(O2);
    a0 = cadd(E0, O0);  a4 = csub(E0, O0);
    a1 = cadd(E1, w1o); a5 = csub(E1, w1o);
    a2 = cadd(E2, m2);  a6 = csub(E2, m2);
    a3 = cadd(E3, w3o); a7 = csub(E3, w3o);
}

// group barrier: 64 threads (2 warps) of signal-group grp, named barrier 1..3
#define GBAR(grp) asm volatile("bar.sync %0, 64;" :: "r"((grp) + 1) : "memory")

// Load one frame's packed complex input (z[n] = x[2n] + i x[2n+1]).
__device__ __forceinline__ void load_frame(
    const float* __restrict__ x, int F, int t64,
    float2& a0, float2& a1, float2& a2, float2& a3,
    float2& a4, float2& a5, float2& a6, float2& a7)
{
    if (F >= 0 && F + NFFT <= LEN) {
        const float2* x2 = (const float2*)(x + F);
        a0 = x2[t64];       a1 = x2[t64 + 64];  a2 = x2[t64 + 128]; a3 = x2[t64 + 192];
        a4 = x2[t64 + 256]; a5 = x2[t64 + 320]; a6 = x2[t64 + 384]; a7 = x2[t64 + 448];
    } else {
#define LOADR(dst, K) { int g = F + 2 * (t64 + 64 * (K));                          \
        int i0 = min(abs(g), REFL2 - g); int i1 = min(abs(g + 1), REFL2 - g - 1);  \
        dst = make_float2(x[i0], x[i1]); }
        LOADR(a0, 0) LOADR(a1, 1) LOADR(a2, 2) LOADR(a3, 3)
        LOADR(a4, 4) LOADR(a5, 5) LOADR(a6, 6) LOADR(a7, 7)
#undef LOADR
    }
}

// ---------------------------------------------------------------------------
// Fused STFT + patch kernel (identical to the 116.8us R15 winner).
// ---------------------------------------------------------------------------
__global__ __launch_bounds__(192, 4) void fused_kernel(
    const float* __restrict__ xs, const float* __restrict__ xt,
    const float* __restrict__ xg)
{
    const int tid = threadIdx.x;
    const int grp = tid / 64;          // which signal
    const int t64 = tid & 63;
    const int pt  = blockIdx.x;        // 1040 = BATCH*NTP
    const int b   = pt / NTP;
    const int tp  = pt - b * NTP;

    __shared__ float2 SH[3][2][576];   // per-signal ping-pong FFT slabs
    __shared__ float2 tw_a[64];        // W64^{n1*c}
    __shared__ float2 tw_b[512];       // [c*64+t64] = W512^{n0*(k0+8c)}
    __shared__ float2 tw_u[512];       // e^{-i pi j/512}
    __shared__ float  pacc[NFP * 3];

    // ---- build twiddle tables (once per block) ----
    for (int idx = tid; idx < 1088; idx += 192) {
        float sn, cs;
        if (idx < 64) {
            int n1 = idx >> 3, c = idx & 7;
            sincospif(-(float)(n1 * c) * (1.0f / 32.0f), &sn, &cs);
            tw_a[idx] = make_float2(cs, sn);
        } else if (idx < 576) {
            int e = idx - 64; int c = e >> 6; int t_ = e & 63;
            int n0b = t_ & 7, k0 = t_ >> 3;
            sincospif(-(float)(n0b * (k0 + 8 * c)) * (1.0f / 256.0f), &sn, &cs);
            tw_b[e] = make_float2(cs, sn);
        } else {
            int j = idx - 576;
            sincospif(-(float)j * (1.0f / 512.0f), &sn, &cs);
            tw_u[j] = make_float2(cs, sn);
        }
    }
    if (tid < NFP * 3) pacc[tid] = 0.f;
    if (pt == 0 && tid == 0) g_done = 0;   // reset merge counter for select
    __syncthreads();

    const float* x = (grp == 0 ? xs : (grp == 1 ? xt : xg)) + (size_t)b * LEN;
    float2* buf0 = SH[grp][0];
    float2* buf1 = SH[grp][1];
    const int n1A = t64 >> 3;
    const int n0A = t64 & 7;

    // per-thread patch accumulators (f = tid, tid+192, tid+384)
    float aS0 = 0.f, aT0 = 0.f, aP0 = 0.f;
    float aS1 = 0.f, aT1 = 0.f, aP1 = 0.f;
    float aS2 = 0.f, aT2 = 0.f, aP2 = 0.f;

    const int t0  = tp * 16;
    const int nfr = min(16, NT - t0);    // 16, or 1 for tp==64

    // ---- preload frame 0 ----
    float2 a0, a1, a2, a3, a4, a5, a6, a7;
    load_frame(x, t0 * HOP - 512, t64, a0, a1, a2, a3, a4, a5, a6, a7);

    for (int it = 0; it < nfr; it++) {
        // ---- step A: FFT8 over n2; twiddle from shared table ----
        fft8(a0, a1, a2, a3, a4, a5, a6, a7);
        a1 = cmul(a1, tw_a[n1A * 8 + 1]);
        a2 = cmul(a2, tw_a[n1A * 8 + 2]);
        a3 = cmul(a3, tw_a[n1A * 8 + 3]);
        a4 = cmul(a4, tw_a[n1A * 8 + 4]);
        a5 = cmul(a5, tw_a[n1A * 8 + 5]);
        a6 = cmul(a6, tw_a[n1A * 8 + 6]);
        a7 = cmul(a7, tw_a[n1A * 8 + 7]);
        {
            const int wi = n1A * 9 + n0A;
            buf0[wi]       = a0; buf0[wi + 72]  = a1; buf0[wi + 144] = a2; buf0[wi + 216] = a3;
            buf0[wi + 288] = a4; buf0[wi + 360] = a5; buf0[wi + 432] = a6; buf0[wi + 504] = a7;
        }
        GBAR(grp);

        // ---- step B: gather over n1; FFT8; twiddle; write buf1 ----
        {
            const int n0b = t64 & 7;
            const int k0  = t64 >> 3;
            const int rb  = k0 * 72 + n0b;
            float2 b0 = buf0[rb];      float2 b1 = buf0[rb + 9];  float2 b2 = buf0[rb + 18];
            float2 b3 = buf0[rb + 27]; float2 b4 = buf0[rb + 36]; float2 b5 = buf0[rb + 45];
            float2 b6 = buf0[rb + 54]; float2 b7 = buf0[rb + 63];
            fft8(b0, b1, b2, b3, b4, b5, b6, b7);
            b0 = cmul(b0, tw_b[t64]);
            b1 = cmul(b1, tw_b[64  + t64]);
            b2 = cmul(b2, tw_b[128 + t64]);
            b3 = cmul(b3, tw_b[192 + t64]);
            b4 = cmul(b4, tw_b[256 + t64]);
            b5 = cmul(b5, tw_b[320 + t64]);
            b6 = cmul(b6, tw_b[384 + t64]);
            b7 = cmul(b7, tw_b[448 + t64]);
            const int wb = k0 * 9 + n0b;
            buf1[wb]       = b0; buf1[wb + 72]  = b1; buf1[wb + 144] = b2; buf1[wb + 216] = b3;
            buf1[wb + 288] = b4; buf1[wb + 360] = b5; buf1[wb + 432] = b6; buf1[wb + 504] = b7;
        }
        GBAR(grp);

        // ---- step C: gather over n0; FFT8 -> Z; publish Z[j] at buf0[j] ----
        {
            const int k0c = t64 & 7;
            const int k1  = t64 >> 3;
            const int rc  = k1 * 72 + k0c * 9;
            float2 c0 = buf1[rc];     float2 c1 = buf1[rc + 1]; float2 c2 = buf1[rc + 2];
            float2 c3 = buf1[rc + 3]; float2 c4 = buf1[rc + 4]; float2 c5 = buf1[rc + 5];
            float2 c6 = buf1[rc + 6]; float2 c7 = buf1[rc + 7];
            fft8(c0, c1, c2, c3, c4, c5, c6, c7);
            buf0[t64]       = c0; buf0[t64 + 64]  = c1; buf0[t64 + 128] = c2; buf0[t64 + 192] = c3;
            buf0[t64 + 256] = c4; buf0[t64 + 320] = c5; buf0[t64 + 384] = c6; buf0[t64 + 448] = c7;
        }

        // ---- PREFETCH next frame's input (overlaps barrier + accumulate) ----
        if (it + 1 < nfr)
            load_frame(x, (t0 + it + 1) * HOP - 512, t64,
                       a0, a1, a2, a3, a4, a5, a6, a7);

        __syncthreads();   // all three signals' Z published

        // ---- fused untangle + accumulate: 3 bands x 3 signals inline ----
#pragma unroll
        for (int bd = 0; bd < 3; bd++) {
            const int f = tid + 192 * bd;
            if (f <= 512) {
                float m[3];
                if (f < 512) {
                    float2 w = tw_u[f];
                    const int fm = (512 - f) & 511;
#pragma unroll
                    for (int sig = 0; sig < 3; sig++) {
                        float2 Zj = SH[sig][0][f];
                        float2 Zm = SH[sig][0][fm];
                        float ex = 0.5f * (Zj.x + Zm.x), ey = 0.5f * (Zj.y - Zm.y);
                        float dx = 0.5f * (Zj.x - Zm.x), dy = 0.5f * (Zj.y + Zm.y);
                        float ox = dy, oy = -dx;
                        float xr_ = ex + (w.x * ox - w.y * oy);
                        float xi_ = ey + (w.x * oy + w.y * ox);
                        m[sig] = fmaxf(sqrtf(xr_ * xr_ + xi_ * xi_), 1e-8f);
                    }
                } else {   // f == 512
#pragma unroll
                    for (int sig = 0; sig < 3; sig++) {
                        float2 Z0 = SH[sig][0][0];
                        m[sig] = fmaxf(fabsf(Z0.x - Z0.y), 1e-8f);
                    }
                }
                float vS = fabsf(m[0] - m[2]);
                float vT = fabsf(m[1] - m[2]);
                float d  = m[0] - m[1];
                float vP = d * d;
                if (bd == 0)      { aS0 += vS; aT0 += vT; aP0 += vP; }
                else if (bd == 1) { aS1 += vS; aT1 += vT; aP1 += vP; }
                else              { aS2 += vS; aT2 += vT; aP2 += vP; }
            }
        }
        __syncthreads();   // protect buf0 before next frame's A-write
    }

    // ---- fold per-thread accumulators into per-f-patch sums ----
    {
        int p0 = tid >> 4;                       // f = tid
        atomicAdd(&pacc[p0 * 3 + 0], aS0);
        atomicAdd(&pacc[p0 * 3 + 1], aT0);
        atomicAdd(&pacc[p0 * 3 + 2], aP0);
        int p1 = (tid + 192) >> 4;               // f = tid+192
        atomicAdd(&pacc[p1 * 3 + 0], aS1);
        atomicAdd(&pacc[p1 * 3 + 1], aT1);
        atomicAdd(&pacc[p1 * 3 + 2], aP1);
        if (tid + 384 <= 512) {                  // f = tid+384
            int p2 = (tid + 384) >> 4;
            atomicAdd(&pacc[p2 * 3 + 0], aS2);
            atomicAdd(&pacc[p2 * 3 + 1], aT2);
            atomicAdd(&pacc[p2 * 3 + 2], aP2);
        }
    }
    __syncthreads();

    if (tid < NFP * 3)
        g_part[(size_t)pt * (NFP * 3) + tid] = pacc[tid];
}

// ---------------------------------------------------------------------------
// Kernel 2: per-batch top-k selection + stats; radix select (4x8-bit passes)
// replaces the 32-iteration binary search. LAST finishing block computes the
// 4 final scalars.
// ---------------------------------------------------------------------------
__device__ __forceinline__ int bredI(int v, int* scr) {
    const int tid = threadIdx.x;
#pragma unroll
    for (int o = 16; o; o >>= 1) v += __shfl_down_sync(0xffffffffu, v, o);
    __syncthreads();
    if ((tid & 31) == 0) scr[tid >> 5] = v;
    __syncthreads();
    int r = 0;
#pragma unroll
    for (int j = 0; j < 8; j++) r += scr[j];
    return r;
}
__device__ __forceinline__ float bredF(float v, float* scr) {
    const int tid = threadIdx.x;
#pragma unroll
    for (int o = 16; o; o >>= 1) v += __shfl_down_sync(0xffffffffu, v, o);
    __syncthreads();
    if ((tid & 31) == 0) scr[tid >> 5] = v;
    __syncthreads();
    float r = 0.f;
#pragma unroll
    for (int j = 0; j < 8; j++) r += scr[j];
    return r;
}

__global__ __launch_bounds__(256) void select_kernel(float* __restrict__ out) {
    const int b = blockIdx.x, tid = threadIdx.x;
    __shared__ unsigned su[NP];
    __shared__ float    spl[NP];
    __shared__ int      eqidx[NP];
    __shared__ int      iscr[8];
    __shared__ float    fscr[8];
    __shared__ int      hist[256];
    __shared__ int      eqc;
    __shared__ int      slast;
    __shared__ int      sbb, sksub;

    float ksum = 0.f; int pcnt = 0;
    for (int i = tid; i < NP; i += 256) {
        int fp = i / NTP, tp = i - fp * NTP;       // patch order p = fp*NTP+tp
        const float* pp = g_part + ((size_t)(b * NTP + tp) * NFP + fp) * 3;
        float kv = (pp[0] - pp[1]) * (1.0f / 256.0f);
        spl[i] = pp[2] * (1.0f / 256.0f);
        unsigned bits = __float_as_uint(kv);
        su[i] = (bits & 0x80000000u) ? ~bits : (bits | 0x80000000u); // order-preserving
        ksum += kv;
        pcnt += (kv > 0.f) ? 1 : 0;
    }
    if (tid == 0) { eqc = 0; slast = 0; }
    __syncthreads();

    ksum = bredF(ksum, fscr);
    pcnt = bredI(pcnt, iscr);

    // ---- radix select: exact KSEL-th largest key (== binary-search v) ----
    unsigned prefix = 0;
    int k = KSEL;
#pragma unroll
    for (int d = 3; d >= 0; d--) {
        hist[tid] = 0;
        __syncthreads();
        const unsigned maskhi = (d == 3) ? 0u : (0xFFFFFFFFu << (8 * (d + 1)));
        for (int i = tid; i < NP; i += 256) {
            unsigned u = su[i];
            if ((u & maskhi) == prefix)
                atomicAdd(&hist[(u >> (8 * d)) & 255u], 1);
        }
        __syncthreads();
        if (tid < 32) {
            const int lane = tid;
            int h0 = hist[lane * 8 + 0], h1 = hist[lane * 8 + 1];
            int h2 = hist[lane * 8 + 2], h3 = hist[lane * 8 + 3];
            int h4 = hist[lane * 8 + 4], h5 = hist[lane * 8 + 5];
            int h6 = hist[lane * 8 + 6], h7 = hist[lane * 8 + 7];
            // suffix sums within lane's 8 bins
            int s7 = h7;
            int s6 = h6 + s7, s5 = h5 + s6, s4 = h4 + s5;
            int s3 = h3 + s4, s2 = h2 + s3, s1 = h1 + s2, s0 = h0 + s1;
            // inclusive suffix scan of lane totals across the warp
            int run = s0;
#pragma unroll
            for (int off = 1; off < 32; off <<= 1) {
                int t2 = __shfl_down_sync(0xffffffffu, run, off);
                if (lane + off < 32) run += t2;
            }
            int above = __shfl_down_sync(0xffffffffu, run, 1);   // lanes > lane
            if (lane == 31) above = 0;
            int Scur[8]  = { s0 + above, s1 + above, s2 + above, s3 + above,
                             s4 + above, s5 + above, s6 + above, s7 + above };
            int Snext[8] = { s1 + above, s2 + above, s3 + above, s4 + above,
                             s5 + above, s6 + above, s7 + above, above };
#pragma unroll
            for (int j = 0; j < 8; j++) {
                if (Scur[j] >= k && Snext[j] < k) {
                    sbb = lane * 8 + j;
                    sksub = Snext[j];
                }
            }
        }
        __syncthreads();
        prefix |= ((unsigned)sbb) << (8 * d);
        k -= sksub;
        __syncthreads();   // protect sbb/sksub before next pass's writes
    }
    const unsigned v = prefix;

    int cgt = 0; float ssel = 0.f;
    for (int i = tid; i < NP; i += 256) {
        unsigned u = su[i];
        if (u > v) { cgt++; ssel += spl[i]; }
        else if (u == v) { int pos = atomicAdd(&eqc, 1); eqidx[pos] = i; }
    }
    cgt  = bredI(cgt, iscr);
    ssel = bredF(ssel, fscr);
    __syncthreads();

    if (tid == 0) {
        int need = KSEL - cgt;         // >= 1 by construction
        int ce   = eqc;
        float extra = 0.f;
        if (need >= ce) {
            for (int j = 0; j < ce; j++) extra += spl[eqidx[j]];
        } else {
            int last = -1;
            for (int t2 = 0; t2 < need; t2++) {
                int mn = 0x7fffffff;
                for (int j = 0; j < ce; j++) {
                    int ix = eqidx[j];
                    if (ix > last && ix < mn) mn = ix;
                }
                extra += spl[mn];
                last = mn;
            }
        }
        g_bsel[b] = (ssel + extra) * (1.0f / (float)KSEL);
        g_bkgs[b] = ksum;
        g_bpos[b] = pcnt;
        __threadfence();
        int prev = atomicAdd(&g_done, 1);
        slast = (prev == BATCH - 1) ? 1 : 0;
    }
    __syncthreads();

    // last block computes the 4 final scalars
    if (slast && tid < 32) {
        __threadfence();
        float s  = (tid < BATCH) ? g_bsel[tid] : 0.f;
        float kg = (tid < BATCH) ? g_bkgs[tid] : 0.f;
        float pc = (tid < BATCH) ? (float)g_bpos[tid] : 0.f;
#pragma unroll
        for (int o = 16; o; o >>= 1) {
            s  += __shfl_down_sync(0xffffffffu, s,  o);
            kg += __shfl_down_sync(0xffffffffu, kg, o);
            pc += __shfl_down_sync(0xffffffffu, pc, o);
        }
        if (tid == 0) {
            out[0] = s * (1.0f / (float)BATCH);                  // loss
            out[1] = (float)KSEL / (float)NP;                    // sel_ratio
            out[2] = kg / (float)(BATCH * NP);                   // kgs_mean
            out[3] = pc / (float)(BATCH * NP);                   // kgs_pos_ratio
        }
    }
}

extern "C" void kernel_launch(void* const* d_in, const int* in_sizes, int n_in,
                              void* d_out, int out_size) {
    const float* xs = (const float*)d_in[0];
    const float* xt = (const float*)d_in[1];
    const float* xg = (const float*)d_in[2];
    float* out = (float*)d_out;

    fused_kernel<<<BATCH * NTP, 192>>>(xs, xt, xg);   // 1040 blocks
    select_kernel<<<BATCH, 256>>>(out);               // radix select + final
}